// round 10
// baseline (speedup 1.0000x reference)
#include <cuda_runtime.h>
#include <cuda_fp16.h>
#include <cstdint>

// ---------------- problem constants ----------------
#define BATCH 32
#define CIN   256
#define COUT  256
#define HH    49
#define WW    49
#define NPIX  2401
#define NDIR  7
#define NV    1801          // valid hex pixels per batch
#define NVP   1856          // padded to 29*64
#define MTILES 29

// ---------------- GEMM tiling ----------------
#define BM 64
#define BN 256
#define BK 64
#define RS 144                     // smem row stride bytes (64 fp16 = 128B + 16B pad)
#define A_BYTES (BM * RS)          // 9216
#define B_BYTES (BN * RS)          // 36864
#define STAGE   (A_BYTES + B_BYTES)           // 46080
#define NSTAGE  2
#define SMEM_BYTES (NSTAGE * STAGE)           // 92160 -> 2 CTAs/SM (184.3K <= 228K)
#define NCHUNK  (NDIR * (CIN / BK))           // 28

// ---------------- scratch (static __device__, allocation-guard safe) ----------------
__device__ __align__(16) __half g_xt[(size_t)BATCH * NVP * CIN];
__device__ __align__(16) __half g_w[NDIR * COUT * CIN];

__constant__ int cDY[NDIR] = {0, 1, 0, -1, -1, 0, 1};
__constant__ int cDX[NDIR] = {0, 0, 1,  1,  0, -1, -1};

// ---------------- hex geometry (closed form, tableless) ----------------
__device__ __forceinline__ int hx_wmin(int h) { return h < 24 ? 24 - h : 0; }
__device__ __forceinline__ int hx_wmax(int h) { return h < 24 ? 48 : 72 - h; }
__device__ __forceinline__ int hx_rowstart(int h) {
    return (h <= 25) ? (h * (49 + h)) / 2
                     : (2101 - ((73 - h) * (74 - h)) / 2);
}
// invert rowstart: h such that rowstart(h) <= ci < rowstart(h+1); valid 0<=ci<NV
__device__ __forceinline__ int hx_h_of(int ci) {
    const bool mir = (ci >= 925);
    const int c = mir ? (1800 - ci) : ci;          // now c < 925, rows 0..24 region
    int h = (int)(0.5f * (sqrtf((float)(2401 + 8 * c)) - 49.0f));
    if (h < 0) h = 0;
    while ((h * (49 + h)) / 2 > c) --h;
    while (((h + 1) * (50 + h)) / 2 <= c) ++h;
    return mir ? (48 - h) : h;
}

// ---------------- PTX helpers (portable sm_80-level) ----------------
__device__ __forceinline__ void cpa16(uint32_t dst, const void* src, int szbytes) {
    asm volatile("cp.async.cg.shared.global [%0], [%1], 16, %2;"
                 :: "r"(dst), "l"(src), "r"(szbytes) : "memory");
}
#define CP_COMMIT() asm volatile("cp.async.commit_group;" ::: "memory")
#define CP_WAIT1()  asm volatile("cp.async.wait_group 1;" ::: "memory")

#define LDSM4(r, addr) \
    asm volatile("ldmatrix.sync.aligned.m8n8.x4.shared.b16 {%0,%1,%2,%3}, [%4];" \
                 : "=r"((r)[0]), "=r"((r)[1]), "=r"((r)[2]), "=r"((r)[3]) : "r"(addr))

#define MMA(d, a, bp) \
    asm volatile("mma.sync.aligned.m16n8k16.row.col.f32.f16.f16.f32 " \
                 "{%0,%1,%2,%3}, {%4,%5,%6,%7}, {%8,%9}, {%0,%1,%2,%3};" \
                 : "+f"((d)[0]), "+f"((d)[1]), "+f"((d)[2]), "+f"((d)[3]) \
                 : "r"((a)[0]), "r"((a)[1]), "r"((a)[2]), "r"((a)[3]), \
                   "r"((bp)[0]), "r"((bp)[1]))

// ---------------- zero-fill output (masked pixels must be 0; d_out poisoned) ----------------
__global__ void zero_out(float4* __restrict__ o, int n4) {
    const int i = blockIdx.x * blockDim.x + threadIdx.x;
    const int stride = gridDim.x * blockDim.x;
    const float4 z = make_float4(0.f, 0.f, 0.f, 0.f);
    for (int k = i; k < n4; k += stride) o[k] = z;
}

// ---------------- preprocessing ----------------
// x [B,C,H,W] fp32 --(hex compact, transpose, fp16 round)--> xt [b][cidx][c]
__global__ void split_x_kernel(const float* __restrict__ x) {
    __shared__ float t[32][33];
    const int pt = blockIdx.x, ct = blockIdx.y, b = blockIdx.z;
    const int p00 = pt * 32, c00 = ct * 32;
    const int tx = threadIdx.x & 31;
    const int ty = threadIdx.x >> 5;

#pragma unroll
    for (int k = 0; k < 4; ++k) {
        const int c = c00 + ty + k * 8;
        const int p = p00 + tx;
        float v = 0.f;
        if (p < NPIX) v = x[((size_t)b * CIN + c) * NPIX + p];
        t[ty + k * 8][tx] = v;
    }
    __syncthreads();
#pragma unroll
    for (int k = 0; k < 4; ++k) {
        const int p = p00 + ty + k * 8;
        if (p >= NPIX) continue;
        const int h = p / WW, w = p - (p / WW) * WW;
        if (w < hx_wmin(h) || w > hx_wmax(h)) continue;   // outside hex: drop
        const int cidx = hx_rowstart(h) + w - hx_wmin(h);
        const int c = c00 + tx;
        g_xt[((size_t)b * NVP + cidx) * CIN + c] = __float2half(t[tx][ty + k * 8]);
    }
}

// weight [O,C,7] fp32 -> [n][o][c] fp16
__global__ void split_w_kernel(const float* __restrict__ w) {
    const int idx = blockIdx.x * blockDim.x + threadIdx.x;
    if (idx >= NDIR * COUT * CIN) return;
    const int c = idx & 255;
    const int o = (idx >> 8) & 255;
    const int n = idx >> 16;
    g_w[idx] = __float2half(w[o * (CIN * NDIR) + c * NDIR + n]);
}

// ---------------- main warp-MMA implicit-GEMM kernel (compacted M, BK=64) ----------------
__global__ __launch_bounds__(256, 2)
void hexconv_mma(const float* __restrict__ bias, float* __restrict__ out) {
    extern __shared__ char smem[];
    const uint32_t sb = (uint32_t)__cvta_generic_to_shared(smem);
    const int tid  = threadIdx.x;
    const int lane = tid & 31;
    const int wid  = tid >> 5;
    const int wm   = wid & 1;      // 2 M groups of 32
    const int wn   = wid >> 1;     // 4 N groups of 64
    const int p0   = blockIdx.x * BM;   // compact-pixel tile base
    const int b    = blockIdx.y;

    // A-load geometry: thread -> (row am = tid/4, 32B chunk akc = tid%4)
    const int am  = tid >> 2;
    const int akc = tid & 3;
    const int ai  = p0 + am;            // compact index (< NVP)
    const bool aiv = (ai < NV);
    const int ah_ = aiv ? hx_h_of(ai) : 0;
    const int aw_ = hx_wmin(ah_) + (ai - hx_rowstart(ah_));

    float acc[2][8][4];
#pragma unroll
    for (int i = 0; i < 2; ++i)
#pragma unroll
        for (int j = 0; j < 8; ++j)
#pragma unroll
            for (int r = 0; r < 4; ++r) acc[i][j][r] = 0.f;

    auto load_chunk = [&](int ch, int s) {
        const int nd = ch >> 2;               // 4 chunks per direction
        const int c0 = (ch & 3) << 6;         // K base (64 per chunk)
        const uint32_t st = sb + (uint32_t)s * STAGE;
        // A: hex-shifted neighbor, zero-filled when invalid (row = 128B, 2 cp per thread)
        const int hh = ah_ + cDY[nd];
        const int ww = aw_ + cDX[nd];
        const bool hv = ((unsigned)hh < HH);
        const int wmn = hv ? hx_wmin(hh) : 0;
        const bool av = aiv && hv && (ww >= wmn) && (ww <= (hv ? hx_wmax(hh) : -1));
        const int src = av ? (hx_rowstart(hh) + ww - wmn) : 0;
        const size_t abase = ((size_t)b * NVP + src) * CIN + c0 + akc * 16;
        const int asz = av ? 16 : 0;
        cpa16(st + am * RS + akc * 32,      g_xt + abase,     asz);
        cpa16(st + am * RS + akc * 32 + 16, g_xt + abase + 8, asz);
        // B: row o = tid, 128B contiguous k (8 cp per thread)
        const size_t bbase = ((size_t)nd * COUT + tid) * CIN + c0;
        const uint32_t bdst = st + A_BYTES + tid * RS;
#pragma unroll
        for (int j = 0; j < 8; ++j)
            cpa16(bdst + j * 16, g_w + bbase + j * 8, 16);
    };

    auto compute_chunk = [&](int s) {
        const uint32_t st = sb + (uint32_t)s * STAGE;
        const uint32_t Ah = st;
        const uint32_t Bh = st + A_BYTES;
#pragma unroll
        for (int ks = 0; ks < 4; ++ks) {
            const int kb = ks * 32;   // 16 fp16 = 32 bytes
            uint32_t ah[2][4], bb[4][4];
            const uint32_t aaddr = Ah + (uint32_t)((wm * 32 + (lane & 15)) * RS)
                                   + kb + ((lane >> 4) << 4);
            LDSM4(ah[0], aaddr);
            LDSM4(ah[1], aaddr + 16 * RS);
            const uint32_t baddr = Bh + (uint32_t)((wn * 64 + ((lane >> 4) << 3) + (lane & 7)) * RS)
                                   + kb + (((lane >> 3) & 1) << 4);
#pragma unroll
            for (int g = 0; g < 4; ++g) LDSM4(bb[g], baddr + g * 16 * RS);
            // single pass: acc += A*B (each acc touched once per k-step)
#pragma unroll
            for (int mi = 0; mi < 2; ++mi)
#pragma unroll
                for (int ni = 0; ni < 8; ++ni)
                    MMA(acc[mi][ni], ah[mi], (&bb[ni >> 1][(ni & 1) * 2]));
        }
    };

    // ---------------- 2-stage pipelined mainloop ----------------
    load_chunk(0, 0);
    CP_COMMIT();
    for (int ch = 0; ch < NCHUNK; ++ch) {
        if (ch + 1 < NCHUNK) load_chunk(ch + 1, (ch + 1) & 1);
        CP_COMMIT();           // committed even when empty (keeps wait semantics)
        CP_WAIT1();            // group ch fully arrived
        __syncthreads();       // visibility of other threads' cp.async data
        compute_chunk(ch & 1);
        __syncthreads();       // stage reusable for load in next iteration
    }

    // ---------------- epilogue: bias add (all compacted rows inside the hex) ----------------
    float bv[16];
#pragma unroll
    for (int ni = 0; ni < 8; ++ni)
#pragma unroll
        for (int j = 0; j < 2; ++j)
            bv[ni * 2 + j] = bias[wn * 64 + ni * 8 + (lane & 3) * 2 + j];

#pragma unroll
    for (int mi = 0; mi < 2; ++mi)
#pragma unroll
        for (int rh = 0; rh < 2; ++rh) {
            const int m = wm * 32 + mi * 16 + (lane >> 2) + rh * 8;
            const int ci = p0 + m;
            if (ci >= NV) continue;
            const int h = hx_h_of(ci);
            const int w = hx_wmin(h) + (ci - hx_rowstart(h));
            const int p = h * WW + w;
#pragma unroll
            for (int ni = 0; ni < 8; ++ni)
#pragma unroll
                for (int j = 0; j < 2; ++j) {
                    const int o = wn * 64 + ni * 8 + (lane & 3) * 2 + j;
                    out[((size_t)b * COUT + o) * NPIX + p] =
                        acc[mi][ni][rh * 2 + j] + bv[ni * 2 + j];
                }
        }
}

// ---------------- launch ----------------
extern "C" void kernel_launch(void* const* d_in, const int* in_sizes, int n_in,
                              void* d_out, int out_size) {
    const float* x    = (const float*)d_in[0];
    const float* wgt  = (const float*)d_in[1];
    const float* bias = (const float*)d_in[2];
    float* out = (float*)d_out;
    (void)in_sizes; (void)n_in;

    cudaFuncSetAttribute(hexconv_mma, cudaFuncAttributeMaxDynamicSharedMemorySize, SMEM_BYTES);

    // launch order chosen so the main kernel sits at position 3 (profiler window)
    zero_out<<<592, 256>>>((float4*)out, out_size / 4);
    split_x_kernel<<<dim3(76, 8, BATCH), 256>>>(x);
    split_w_kernel<<<(NDIR * COUT * CIN + 255) / 256, 256>>>(wgt);
    hexconv_mma<<<dim3(MTILES, BATCH), 256, SMEM_BYTES>>>(bias, out);
}

// round 13
// speedup vs baseline: 1.1688x; 1.1688x over previous
#include <cuda_runtime.h>
#include <cuda_fp16.h>
#include <cstdint>

// ---------------- problem constants ----------------
#define BATCH 32
#define CIN   256
#define COUT  256
#define HH    49
#define WW    49
#define NPIX  2401
#define NDIR  7
#define NV    1801          // valid hex pixels per batch
#define NVP   1856          // padded to 29*64
#define MTILES 29

// ---------------- GEMM tiling ----------------
#define THREADS 512
#define BM 64
#define BN 256
#define BK 64
#define RS 144                     // smem row stride bytes (64 fp16 = 128B + 16B pad)
#define A_BYTES (BM * RS)          // 9216
#define B_BYTES (BN * RS)          // 36864
#define STAGE   (A_BYTES + B_BYTES)           // 46080
#define NSTAGE  2
#define SMEM_BYTES (NSTAGE * STAGE)           // 92160 -> 2 CTAs/SM (184.3K <= 228K)
#define NCHUNK  (NDIR * (CIN / BK))           // 28

// ---------------- scratch (static __device__, allocation-guard safe) ----------------
__device__ __align__(16) __half g_xt[(size_t)BATCH * NVP * CIN];
__device__ __align__(16) __half g_w[NDIR * COUT * CIN];

__constant__ int cDY[NDIR] = {0, 1, 0, -1, -1, 0, 1};
__constant__ int cDX[NDIR] = {0, 0, 1,  1,  0, -1, -1};

// ---------------- hex geometry (closed form, tableless) ----------------
__device__ __forceinline__ int hx_wmin(int h) { return h < 24 ? 24 - h : 0; }
__device__ __forceinline__ int hx_wmax(int h) { return h < 24 ? 48 : 72 - h; }
__device__ __forceinline__ int hx_rowstart(int h) {
    return (h <= 25) ? (h * (49 + h)) / 2
                     : (2101 - ((73 - h) * (74 - h)) / 2);
}
// invert rowstart: h such that rowstart(h) <= ci < rowstart(h+1); valid 0<=ci<NV
__device__ __forceinline__ int hx_h_of(int ci) {
    const bool mir = (ci >= 925);
    const int c = mir ? (1800 - ci) : ci;          // now c < 925, rows 0..24 region
    int h = (int)(0.5f * (sqrtf((float)(2401 + 8 * c)) - 49.0f));
    if (h < 0) h = 0;
    while ((h * (49 + h)) / 2 > c) --h;
    while (((h + 1) * (50 + h)) / 2 <= c) ++h;
    return mir ? (48 - h) : h;
}

// ---------------- PTX helpers (portable sm_80-level) ----------------
__device__ __forceinline__ void cpa16(uint32_t dst, const void* src, int szbytes) {
    asm volatile("cp.async.cg.shared.global [%0], [%1], 16, %2;"
                 :: "r"(dst), "l"(src), "r"(szbytes) : "memory");
}
#define CP_COMMIT() asm volatile("cp.async.commit_group;" ::: "memory")
#define CP_WAIT1()  asm volatile("cp.async.wait_group 1;" ::: "memory")

#define LDSM4(r, addr) \
    asm volatile("ldmatrix.sync.aligned.m8n8.x4.shared.b16 {%0,%1,%2,%3}, [%4];" \
                 : "=r"((r)[0]), "=r"((r)[1]), "=r"((r)[2]), "=r"((r)[3]) : "r"(addr))

#define MMA(d, a, bp) \
    asm volatile("mma.sync.aligned.m16n8k16.row.col.f32.f16.f16.f32 " \
                 "{%0,%1,%2,%3}, {%4,%5,%6,%7}, {%8,%9}, {%0,%1,%2,%3};" \
                 : "+f"((d)[0]), "+f"((d)[1]), "+f"((d)[2]), "+f"((d)[3]) \
                 : "r"((a)[0]), "r"((a)[1]), "r"((a)[2]), "r"((a)[3]), \
                   "r"((bp)[0]), "r"((bp)[1]))

// ---------------- zero-fill output (masked pixels must be 0; d_out poisoned) ----------------
__global__ void zero_out(float4* __restrict__ o, int n4) {
    const int i = blockIdx.x * blockDim.x + threadIdx.x;
    const int stride = gridDim.x * blockDim.x;
    const float4 z = make_float4(0.f, 0.f, 0.f, 0.f);
    for (int k = i; k < n4; k += stride) o[k] = z;
}

// ---------------- preprocessing ----------------
// x [B,C,H,W] fp32 --(hex compact, transpose, fp16 round)--> xt [b][cidx][c]
__global__ void split_x_kernel(const float* __restrict__ x) {
    __shared__ float t[32][33];
    const int pt = blockIdx.x, ct = blockIdx.y, b = blockIdx.z;
    const int p00 = pt * 32, c00 = ct * 32;
    const int tx = threadIdx.x & 31;
    const int ty = threadIdx.x >> 5;

#pragma unroll
    for (int k = 0; k < 4; ++k) {
        const int c = c00 + ty + k * 8;
        const int p = p00 + tx;
        float v = 0.f;
        if (p < NPIX) v = x[((size_t)b * CIN + c) * NPIX + p];
        t[ty + k * 8][tx] = v;
    }
    __syncthreads();
#pragma unroll
    for (int k = 0; k < 4; ++k) {
        const int p = p00 + ty + k * 8;
        if (p >= NPIX) continue;
        const int h = p / WW, w = p - (p / WW) * WW;
        if (w < hx_wmin(h) || w > hx_wmax(h)) continue;   // outside hex: drop
        const int cidx = hx_rowstart(h) + w - hx_wmin(h);
        const int c = c00 + tx;
        g_xt[((size_t)b * NVP + cidx) * CIN + c] = __float2half(t[tx][ty + k * 8]);
    }
}

// weight [O,C,7] fp32 -> [n][o][c] fp16
__global__ void split_w_kernel(const float* __restrict__ w) {
    const int idx = blockIdx.x * blockDim.x + threadIdx.x;
    if (idx >= NDIR * COUT * CIN) return;
    const int c = idx & 255;
    const int o = (idx >> 8) & 255;
    const int n = idx >> 16;
    g_w[idx] = __float2half(w[o * (CIN * NDIR) + c * NDIR + n]);
}

// ---------------- main warp-MMA implicit-GEMM kernel (512 thr, warp tile 32x32) ----------------
__global__ __launch_bounds__(THREADS, 2)
void hexconv_mma(const float* __restrict__ bias, float* __restrict__ out) {
    extern __shared__ char smem[];
    const uint32_t sb = (uint32_t)__cvta_generic_to_shared(smem);
    const int tid  = threadIdx.x;
    const int lane = tid & 31;
    const int wid  = tid >> 5;     // 0..15
    const int wm   = wid & 1;      // 2 M groups of 32 rows
    const int wn   = wid >> 1;     // 8 N groups of 32 cols
    const int p0   = blockIdx.x * BM;   // compact-pixel tile base
    const int b    = blockIdx.y;

    // A-load geometry: thread -> (row am = tid/8, 16B chunk akc = tid%8); 1 cp each
    const int am  = tid >> 3;
    const int akc = tid & 7;
    const int ai  = p0 + am;            // compact index (< NVP)
    const bool aiv = (ai < NV);
    const int ah_ = aiv ? hx_h_of(ai) : 0;
    const int aw_ = hx_wmin(ah_) + (ai - hx_rowstart(ah_));

    // B-load geometry: thread -> (row br = tid/2, 64B half bh = tid%2); 4 cp each
    const int br = tid >> 1;
    const int bh = tid & 1;

    float acc[2][4][4];
#pragma unroll
    for (int i = 0; i < 2; ++i)
#pragma unroll
        for (int j = 0; j < 4; ++j)
#pragma unroll
            for (int r = 0; r < 4; ++r) acc[i][j][r] = 0.f;

    auto load_chunk = [&](int ch, int s) {
        const int nd = ch >> 2;               // 4 chunks per direction
        const int c0 = (ch & 3) << 6;         // K base (64 per chunk)
        const uint32_t st = sb + (uint32_t)s * STAGE;
        // A: hex-shifted neighbor, zero-filled when invalid (1 cp of 16B per thread)
        const int hh = ah_ + cDY[nd];
        const int ww = aw_ + cDX[nd];
        const bool hv = ((unsigned)hh < HH);
        const int wmn = hv ? hx_wmin(hh) : 0;
        const bool av = aiv && hv && (ww >= wmn) && (ww <= (hv ? hx_wmax(hh) : -1));
        const int src = av ? (hx_rowstart(hh) + ww - wmn) : 0;
        const size_t abase = ((size_t)b * NVP + src) * CIN + c0 + akc * 8;
        cpa16(st + am * RS + akc * 16, g_xt + abase, av ? 16 : 0);
        // B: row o = br, 64B half (4 cp per thread)
        const size_t bbase = ((size_t)nd * COUT + br) * CIN + c0 + bh * 32;
        const uint32_t bdst = st + A_BYTES + br * RS + bh * 64;
#pragma unroll
        for (int j = 0; j < 4; ++j)
            cpa16(bdst + j * 16, g_w + bbase + j * 8, 16);
    };

    auto compute_chunk = [&](int s) {
        const uint32_t st = sb + (uint32_t)s * STAGE;
        const uint32_t Ah = st;
        const uint32_t Bh = st + A_BYTES;
#pragma unroll
        for (int ks = 0; ks < 4; ++ks) {
            const int kb = ks * 32;   // 16 fp16 = 32 bytes
            uint32_t ah[2][4], bb[2][4];
            const uint32_t aaddr = Ah + (uint32_t)((wm * 32 + (lane & 15)) * RS)
                                   + kb + ((lane >> 4) << 4);
            LDSM4(ah[0], aaddr);
            LDSM4(ah[1], aaddr + 16 * RS);
            const uint32_t baddr = Bh + (uint32_t)((wn * 32 + ((lane >> 4) << 3) + (lane & 7)) * RS)
                                   + kb + (((lane >> 3) & 1) << 4);
            LDSM4(bb[0], baddr);
            LDSM4(bb[1], baddr + 16 * RS);
            // single pass: acc += A*B (each acc touched once per k-step)
#pragma unroll
            for (int mi = 0; mi < 2; ++mi)
#pragma unroll
                for (int ni = 0; ni < 4; ++ni)
                    MMA(acc[mi][ni], ah[mi], (&bb[ni >> 1][(ni & 1) * 2]));
        }
    };

    // ---------------- 2-stage pipelined mainloop ----------------
    load_chunk(0, 0);
    CP_COMMIT();
    for (int ch = 0; ch < NCHUNK; ++ch) {
        if (ch + 1 < NCHUNK) load_chunk(ch + 1, (ch + 1) & 1);
        CP_COMMIT();           // committed even when empty (keeps wait semantics)
        CP_WAIT1();            // group ch fully arrived
        __syncthreads();       // visibility of other threads' cp.async data
        compute_chunk(ch & 1);
        __syncthreads();       // stage reusable for load in next iteration
    }

    // ---------------- epilogue: bias add (all compacted rows inside the hex) ----------------
    float bv[8];
#pragma unroll
    for (int ni = 0; ni < 4; ++ni)
#pragma unroll
        for (int j = 0; j < 2; ++j)
            bv[ni * 2 + j] = bias[wn * 32 + ni * 8 + (lane & 3) * 2 + j];

#pragma unroll
    for (int mi = 0; mi < 2; ++mi)
#pragma unroll
        for (int rh = 0; rh < 2; ++rh) {
            const int m = wm * 32 + mi * 16 + (lane >> 2) + rh * 8;
            const int ci = p0 + m;
            if (ci >= NV) continue;
            const int h = hx_h_of(ci);
            const int w = hx_wmin(h) + (ci - hx_rowstart(h));
            const int p = h * WW + w;
#pragma unroll
            for (int ni = 0; ni < 4; ++ni)
#pragma unroll
                for (int j = 0; j < 2; ++j) {
                    const int o = wn * 32 + ni * 8 + (lane & 3) * 2 + j;
                    out[((size_t)b * COUT + o) * NPIX + p] =
                        acc[mi][ni][rh * 2 + j] + bv[ni * 2 + j];
                }
        }
}

// ---------------- launch ----------------
extern "C" void kernel_launch(void* const* d_in, const int* in_sizes, int n_in,
                              void* d_out, int out_size) {
    const float* x    = (const float*)d_in[0];
    const float* wgt  = (const float*)d_in[1];
    const float* bias = (const float*)d_in[2];
    float* out = (float*)d_out;
    (void)in_sizes; (void)n_in;

    cudaFuncSetAttribute(hexconv_mma, cudaFuncAttributeMaxDynamicSharedMemorySize, SMEM_BYTES);

    // launch order keeps the main kernel at position 3 (profiler window)
    zero_out<<<592, 256>>>((float4*)out, out_size / 4);
    split_x_kernel<<<dim3(76, 8, BATCH), 256>>>(x);
    split_w_kernel<<<(NDIR * COUT * CIN + 255) / 256, 256>>>(wgt);
    hexconv_mma<<<dim3(MTILES, BATCH), THREADS, SMEM_BYTES>>>(bias, out);
}

// round 14
// speedup vs baseline: 1.2408x; 1.0616x over previous
#include <cuda_runtime.h>
#include <cuda_fp16.h>
#include <cstdint>

// ---------------- problem constants ----------------
#define BATCH 32
#define CIN   256
#define COUT  256
#define HH    49
#define WW    49
#define NPIX  2401
#define NDIR  7
#define NV    1801          // valid hex pixels per batch
#define NVP   1856          // padded to 29*64
#define MTILES 29

// ---------------- GEMM tiling ----------------
#define THREADS 512
#define BM 64
#define BN 256
#define BK 32
#define RS 80                      // smem row stride bytes (32 fp16 = 64B + 16B pad)
#define A_BYTES (BM * RS)          // 5120
#define B_BYTES (BN * RS)          // 20480
#define STAGE   (A_BYTES + B_BYTES)           // 25600
#define NSTAGE  4
#define SMEM_BYTES (NSTAGE * STAGE)           // 102400 -> 2 CTAs/SM (204.8K <= 228K)
#define NCHUNK  (NDIR * (CIN / BK))           // 56

// ---------------- scratch (static __device__, allocation-guard safe) ----------------
__device__ __align__(16) __half g_xt[(size_t)BATCH * NVP * CIN];
__device__ __align__(16) __half g_w[NDIR * COUT * CIN];

__constant__ int cDY[NDIR] = {0, 1, 0, -1, -1, 0, 1};
__constant__ int cDX[NDIR] = {0, 0, 1,  1,  0, -1, -1};

// ---------------- hex geometry (closed form, tableless) ----------------
__device__ __forceinline__ int hx_wmin(int h) { return h < 24 ? 24 - h : 0; }
__device__ __forceinline__ int hx_wmax(int h) { return h < 24 ? 48 : 72 - h; }
__device__ __forceinline__ int hx_rowstart(int h) {
    return (h <= 25) ? (h * (49 + h)) / 2
                     : (2101 - ((73 - h) * (74 - h)) / 2);
}
// invert rowstart: h such that rowstart(h) <= ci < rowstart(h+1); valid 0<=ci<NV
__device__ __forceinline__ int hx_h_of(int ci) {
    const bool mir = (ci >= 925);
    const int c = mir ? (1800 - ci) : ci;          // now c < 925, rows 0..24 region
    int h = (int)(0.5f * (sqrtf((float)(2401 + 8 * c)) - 49.0f));
    if (h < 0) h = 0;
    while ((h * (49 + h)) / 2 > c) --h;
    while (((h + 1) * (50 + h)) / 2 <= c) ++h;
    return mir ? (48 - h) : h;
}

// ---------------- PTX helpers (portable sm_80-level) ----------------
__device__ __forceinline__ void cpa16(uint32_t dst, const void* src, int szbytes) {
    asm volatile("cp.async.cg.shared.global [%0], [%1], 16, %2;"
                 :: "r"(dst), "l"(src), "r"(szbytes) : "memory");
}
#define CP_COMMIT() asm volatile("cp.async.commit_group;" ::: "memory")
#define CP_WAIT2()  asm volatile("cp.async.wait_group 2;" ::: "memory")
#define CP_WAIT0()  asm volatile("cp.async.wait_group 0;" ::: "memory")

#define LDSM4(r, addr) \
    asm volatile("ldmatrix.sync.aligned.m8n8.x4.shared.b16 {%0,%1,%2,%3}, [%4];" \
                 : "=r"((r)[0]), "=r"((r)[1]), "=r"((r)[2]), "=r"((r)[3]) : "r"(addr))

#define MMA(d, a, bp) \
    asm volatile("mma.sync.aligned.m16n8k16.row.col.f32.f16.f16.f32 " \
                 "{%0,%1,%2,%3}, {%4,%5,%6,%7}, {%8,%9}, {%0,%1,%2,%3};" \
                 : "+f"((d)[0]), "+f"((d)[1]), "+f"((d)[2]), "+f"((d)[3]) \
                 : "r"((a)[0]), "r"((a)[1]), "r"((a)[2]), "r"((a)[3]), \
                   "r"((bp)[0]), "r"((bp)[1]))

// ---------------- zero only the out-of-hex outputs (disjoint from GEMM writes) ----------------
__global__ void zero_mask(float* __restrict__ out) {
    // one block per (b, o) plane
    float* plane = out + (size_t)blockIdx.x * NPIX;
    for (int p = threadIdx.x; p < NPIX; p += blockDim.x) {
        const int h = p / WW, w = p - (p / WW) * WW;
        if (w < hx_wmin(h) || w > hx_wmax(h)) plane[p] = 0.f;
    }
}

// ---------------- preprocessing ----------------
// x [B,C,H,W] fp32 --(hex compact, transpose, fp16 round)--> xt [b][cidx][c]
__global__ void split_x_kernel(const float* __restrict__ x) {
    __shared__ float t[32][33];
    const int pt = blockIdx.x, ct = blockIdx.y, b = blockIdx.z;
    const int p00 = pt * 32, c00 = ct * 32;
    const int tx = threadIdx.x & 31;
    const int ty = threadIdx.x >> 5;

#pragma unroll
    for (int k = 0; k < 4; ++k) {
        const int c = c00 + ty + k * 8;
        const int p = p00 + tx;
        float v = 0.f;
        if (p < NPIX) v = x[((size_t)b * CIN + c) * NPIX + p];
        t[ty + k * 8][tx] = v;
    }
    __syncthreads();
#pragma unroll
    for (int k = 0; k < 4; ++k) {
        const int p = p00 + ty + k * 8;
        if (p >= NPIX) continue;
        const int h = p / WW, w = p - (p / WW) * WW;
        if (w < hx_wmin(h) || w > hx_wmax(h)) continue;   // outside hex: drop
        const int cidx = hx_rowstart(h) + w - hx_wmin(h);
        const int c = c00 + tx;
        g_xt[((size_t)b * NVP + cidx) * CIN + c] = __float2half(t[tx][ty + k * 8]);
    }
}

// weight [O,C,7] fp32 -> [n][o][c] fp16
__global__ void split_w_kernel(const float* __restrict__ w) {
    const int idx = blockIdx.x * blockDim.x + threadIdx.x;
    if (idx >= NDIR * COUT * CIN) return;
    const int c = idx & 255;
    const int o = (idx >> 8) & 255;
    const int n = idx >> 16;
    g_w[idx] = __float2half(w[o * (CIN * NDIR) + c * NDIR + n]);
}

// ---------------- main warp-MMA implicit-GEMM kernel (512 thr, 4-stage ring) ----------------
__global__ __launch_bounds__(THREADS, 2)
void hexconv_mma(const float* __restrict__ bias, float* __restrict__ out) {
    extern __shared__ char smem[];
    const uint32_t sb = (uint32_t)__cvta_generic_to_shared(smem);
    const int tid  = threadIdx.x;
    const int lane = tid & 31;
    const int wid  = tid >> 5;     // 0..15
    const int wm   = wid & 1;      // 2 M groups of 32 rows
    const int wn   = wid >> 1;     // 8 N groups of 32 cols
    const int p0   = blockIdx.x * BM;   // compact-pixel tile base
    const int b    = blockIdx.y;

    // A-load geometry: threads 0-255 -> (row am = tid/4, 16B chunk akc = tid%4)
    const int am  = tid >> 2;           // valid rows for tid < 256
    const int akc = tid & 3;
    const int ai  = p0 + (am & 63);
    const bool aown = (tid < 256);
    const bool aiv = aown && (ai < NV);
    const int ah_ = aiv ? hx_h_of(ai) : 0;
    const int aw_ = hx_wmin(ah_) + (ai - hx_rowstart(ah_));

    // B-load geometry: all 512 threads -> (row br = tid/2, 32B half bh = tid%2)
    const int br = tid >> 1;
    const int bh = tid & 1;

    float acc[2][4][4];
#pragma unroll
    for (int i = 0; i < 2; ++i)
#pragma unroll
        for (int j = 0; j < 4; ++j)
#pragma unroll
            for (int r = 0; r < 4; ++r) acc[i][j][r] = 0.f;

    auto load_chunk = [&](int ch, int s) {
        const int nd = ch >> 3;               // 8 chunks per direction
        const int c0 = (ch & 7) << 5;         // K base (32 per chunk)
        const uint32_t st = sb + (uint32_t)s * STAGE;
        // A: hex-shifted neighbor, zero-filled when invalid (threads 0-255, 1x16B)
        if (aown) {
            const int hh = ah_ + cDY[nd];
            const int ww = aw_ + cDX[nd];
            const bool hv = ((unsigned)hh < HH);
            const int wmn = hv ? hx_wmin(hh) : 0;
            const bool av = aiv && hv && (ww >= wmn) && (ww <= (hv ? hx_wmax(hh) : -1));
            const int src = av ? (hx_rowstart(hh) + ww - wmn) : 0;
            const size_t abase = ((size_t)b * NVP + src) * CIN + c0 + akc * 8;
            cpa16(st + am * RS + akc * 16, g_xt + abase, av ? 16 : 0);
        }
        // B: row o = br, 32B half (2x16B per thread)
        const size_t bbase = ((size_t)nd * COUT + br) * CIN + c0 + bh * 16;
        const uint32_t bdst = st + A_BYTES + br * RS + bh * 32;
        cpa16(bdst,      g_w + bbase,     16);
        cpa16(bdst + 16, g_w + bbase + 8, 16);
    };

    auto compute_chunk = [&](int s) {
        const uint32_t st = sb + (uint32_t)s * STAGE;
        const uint32_t Ah = st;
        const uint32_t Bh = st + A_BYTES;
        const uint32_t aaddr = Ah + (uint32_t)((wm * 32 + (lane & 15)) * RS)
                               + ((lane >> 4) << 4);
        const uint32_t baddr = Bh + (uint32_t)((wn * 32 + ((lane >> 4) << 3) + (lane & 7)) * RS)
                               + (((lane >> 3) & 1) << 4);
        // issue all fragment loads for both k-steps, then all MMAs (ptxas staggers)
        uint32_t ah0[2][4], bb0[2][4], ah1[2][4], bb1[2][4];
        LDSM4(ah0[0], aaddr);
        LDSM4(ah0[1], aaddr + 16 * RS);
        LDSM4(bb0[0], baddr);
        LDSM4(bb0[1], baddr + 16 * RS);
        LDSM4(ah1[0], aaddr + 32);
        LDSM4(ah1[1], aaddr + 32 + 16 * RS);
        LDSM4(bb1[0], baddr + 32);
        LDSM4(bb1[1], baddr + 32 + 16 * RS);
#pragma unroll
        for (int mi = 0; mi < 2; ++mi)
#pragma unroll
            for (int ni = 0; ni < 4; ++ni)
                MMA(acc[mi][ni], ah0[mi], (&bb0[ni >> 1][(ni & 1) * 2]));
#pragma unroll
        for (int mi = 0; mi < 2; ++mi)
#pragma unroll
            for (int ni = 0; ni < 4; ++ni)
                MMA(acc[mi][ni], ah1[mi], (&bb1[ni >> 1][(ni & 1) * 2]));
    };

    // ---------------- 4-stage ring, 1 sync per chunk, 2 chunks in flight ----------------
    load_chunk(0, 0); CP_COMMIT();
    load_chunk(1, 1); CP_COMMIT();
    for (int ch = 0; ch < NCHUNK; ++ch) {
        if (ch + 2 < NCHUNK) load_chunk(ch + 2, (ch + 2) & 3);
        CP_COMMIT();           // one group per iteration (empty near tail is fine)
        CP_WAIT2();            // group ch complete; ch+1, ch+2 may be outstanding
        __syncthreads();       // all warps see stage ch; also gates ring reuse
        compute_chunk(ch & 3);
    }

    // ---------------- epilogue: bias add (all compacted rows inside the hex) ----------------
    float bv[8];
#pragma unroll
    for (int ni = 0; ni < 4; ++ni)
#pragma unroll
        for (int j = 0; j < 2; ++j)
            bv[ni * 2 + j] = bias[wn * 32 + ni * 8 + (lane & 3) * 2 + j];

#pragma unroll
    for (int mi = 0; mi < 2; ++mi)
#pragma unroll
        for (int rh = 0; rh < 2; ++rh) {
            const int m = wm * 32 + mi * 16 + (lane >> 2) + rh * 8;
            const int ci = p0 + m;
            if (ci >= NV) continue;
            const int h = hx_h_of(ci);
            const int w = hx_wmin(h) + (ci - hx_rowstart(h));
            const int p = h * WW + w;
#pragma unroll
            for (int ni = 0; ni < 4; ++ni)
#pragma unroll
                for (int j = 0; j < 2; ++j) {
                    const int o = wn * 32 + ni * 8 + (lane & 3) * 2 + j;
                    out[((size_t)b * COUT + o) * NPIX + p] =
                        acc[mi][ni][rh * 2 + j] + bv[ni * 2 + j];
                }
        }
}

// ---------------- launch ----------------
extern "C" void kernel_launch(void* const* d_in, const int* in_sizes, int n_in,
                              void* d_out, int out_size) {
    const float* x    = (const float*)d_in[0];
    const float* wgt  = (const float*)d_in[1];
    const float* bias = (const float*)d_in[2];
    float* out = (float*)d_out;
    (void)in_sizes; (void)n_in; (void)out_size;

    cudaFuncSetAttribute(hexconv_mma, cudaFuncAttributeMaxDynamicSharedMemorySize, SMEM_BYTES);

    // launch order keeps the main kernel at position 3 (profiler window)
    zero_mask<<<BATCH * COUT, 256>>>(out);
    split_x_kernel<<<dim3(76, 8, BATCH), 256>>>(x);
    split_w_kernel<<<(NDIR * COUT * CIN + 255) / 256, 256>>>(wgt);
    hexconv_mma<<<dim3(MTILES, BATCH), THREADS, SMEM_BYTES>>>(bias, out);
}

// round 15
// speedup vs baseline: 1.2558x; 1.0121x over previous
#include <cuda_runtime.h>
#include <cuda_fp16.h>
#include <cstdint>

// ---------------- problem constants ----------------
#define BATCH 32
#define CIN   256
#define COUT  256
#define HH    49
#define WW    49
#define NPIX  2401
#define NDIR  7
#define NV    1801          // valid hex pixels per batch
#define NVP   1856          // padded to 29*64
#define MTILES 29

// ---------------- GEMM tiling ----------------
#define THREADS 512
#define BM 64
#define BN 256
#define BK 32
#define RS 80                      // smem row stride bytes (32 fp16 = 64B + 16B pad)
#define A_BYTES (BM * RS)          // 5120
#define B_BYTES (BN * RS)          // 20480
#define STAGE   (A_BYTES + B_BYTES)           // 25600
#define NSTAGE  4
#define SMEM_BYTES (NSTAGE * STAGE)           // 102400 -> 2 CTAs/SM (204.8K <= 228K)
#define NCHUNK  (NDIR * (CIN / BK))           // 56

// ---------------- scratch (static __device__, allocation-guard safe) ----------------
__device__ __align__(16) __half g_xt[(size_t)BATCH * NVP * CIN];
__device__ __align__(16) __half g_w[NDIR * COUT * CIN];

__constant__ int cDY[NDIR] = {0, 1, 0, -1, -1, 0, 1};
__constant__ int cDX[NDIR] = {0, 0, 1,  1,  0, -1, -1};

// ---------------- hex geometry (closed form, tableless) ----------------
__device__ __forceinline__ int hx_wmin(int h) { return h < 24 ? 24 - h : 0; }
__device__ __forceinline__ int hx_wmax(int h) { return h < 24 ? 48 : 72 - h; }
__device__ __forceinline__ int hx_rowstart(int h) {
    return (h <= 25) ? (h * (49 + h)) / 2
                     : (2101 - ((73 - h) * (74 - h)) / 2);
}
// invert rowstart: h such that rowstart(h) <= ci < rowstart(h+1); valid 0<=ci<NV
__device__ __forceinline__ int hx_h_of(int ci) {
    const bool mir = (ci >= 925);
    const int c = mir ? (1800 - ci) : ci;          // now c < 925, rows 0..24 region
    int h = (int)(0.5f * (sqrtf((float)(2401 + 8 * c)) - 49.0f));
    if (h < 0) h = 0;
    while ((h * (49 + h)) / 2 > c) --h;
    while (((h + 1) * (50 + h)) / 2 <= c) ++h;
    return mir ? (48 - h) : h;
}

// ---------------- PTX helpers (portable sm_80-level) ----------------
__device__ __forceinline__ void cpa16(uint32_t dst, const void* src, int szbytes) {
    asm volatile("cp.async.cg.shared.global [%0], [%1], 16, %2;"
                 :: "r"(dst), "l"(src), "r"(szbytes) : "memory");
}
#define CP_COMMIT() asm volatile("cp.async.commit_group;" ::: "memory")
#define CP_WAIT2()  asm volatile("cp.async.wait_group 2;" ::: "memory")

#define LDSM4(r, addr) \
    asm volatile("ldmatrix.sync.aligned.m8n8.x4.shared.b16 {%0,%1,%2,%3}, [%4];" \
                 : "=r"((r)[0]), "=r"((r)[1]), "=r"((r)[2]), "=r"((r)[3]) : "r"(addr))

#define MMA(d, a, bp) \
    asm volatile("mma.sync.aligned.m16n8k16.row.col.f32.f16.f16.f32 " \
                 "{%0,%1,%2,%3}, {%4,%5,%6,%7}, {%8,%9}, {%0,%1,%2,%3};" \
                 : "+f"((d)[0]), "+f"((d)[1]), "+f"((d)[2]), "+f"((d)[3]) \
                 : "r"((a)[0]), "r"((a)[1]), "r"((a)[2]), "r"((a)[3]), \
                   "r"((bp)[0]), "r"((bp)[1]))

// ---------------- zero only the out-of-hex outputs (disjoint from GEMM writes) ----------------
__global__ void zero_mask(float* __restrict__ out) {
    float* plane = out + (size_t)blockIdx.x * NPIX;
    for (int p = threadIdx.x; p < NPIX; p += blockDim.x) {
        const int h = p / WW, w = p - (p / WW) * WW;
        if (w < hx_wmin(h) || w > hx_wmax(h)) plane[p] = 0.f;
    }
}

// ---------------- preprocessing ----------------
// x [B,C,H,W] fp32 --(hex compact, transpose, fp16 round)--> xt [b][cidx][c]
__global__ void split_x_kernel(const float* __restrict__ x) {
    __shared__ float t[32][33];
    const int pt = blockIdx.x, ct = blockIdx.y, b = blockIdx.z;
    const int p00 = pt * 32, c00 = ct * 32;
    const int tx = threadIdx.x & 31;
    const int ty = threadIdx.x >> 5;

#pragma unroll
    for (int k = 0; k < 4; ++k) {
        const int c = c00 + ty + k * 8;
        const int p = p00 + tx;
        float v = 0.f;
        if (p < NPIX) v = x[((size_t)b * CIN + c) * NPIX + p];
        t[ty + k * 8][tx] = v;
    }
    __syncthreads();
#pragma unroll
    for (int k = 0; k < 4; ++k) {
        const int p = p00 + ty + k * 8;
        if (p >= NPIX) continue;
        const int h = p / WW, w = p - (p / WW) * WW;
        if (w < hx_wmin(h) || w > hx_wmax(h)) continue;   // outside hex: drop
        const int cidx = hx_rowstart(h) + w - hx_wmin(h);
        const int c = c00 + tx;
        g_xt[((size_t)b * NVP + cidx) * CIN + c] = __float2half(t[tx][ty + k * 8]);
    }
}

// weight [O,C,7] fp32 -> [n][o][c] fp16
__global__ void split_w_kernel(const float* __restrict__ w) {
    const int idx = blockIdx.x * blockDim.x + threadIdx.x;
    if (idx >= NDIR * COUT * CIN) return;
    const int c = idx & 255;
    const int o = (idx >> 8) & 255;
    const int n = idx >> 16;
    g_w[idx] = __float2half(w[o * (CIN * NDIR) + c * NDIR + n]);
}

// ---------------- main warp-MMA implicit-GEMM kernel (hoisted induction addressing) ----------------
__global__ __launch_bounds__(THREADS, 2)
void hexconv_mma(const float* __restrict__ bias, float* __restrict__ out) {
    extern __shared__ char smem[];
    const uint32_t sb = (uint32_t)__cvta_generic_to_shared(smem);
    const int tid  = threadIdx.x;
    const int lane = tid & 31;
    const int wid  = tid >> 5;     // 0..15
    const int wm   = wid & 1;      // 2 M groups of 32 rows
    const int wn   = wid >> 1;     // 8 N groups of 32 cols
    const int p0   = blockIdx.x * BM;   // compact-pixel tile base
    const int b    = blockIdx.y;

    // A-load geometry: threads 0-255 -> (row am = tid/4, 16B chunk akc = tid%4)
    const int am  = tid >> 2;
    const int akc = tid & 3;
    const int ai  = p0 + (am & 63);
    const bool aown = (tid < 256);
    const bool aiv = aown && (ai < NV);
    const int ah_ = aiv ? hx_h_of(ai) : 0;
    const int aw_ = hx_wmin(ah_) + (ai - hx_rowstart(ah_));

    // B-load geometry: all 512 threads -> (row br = tid/2, 32B half bh = tid%2)
    const int br = tid >> 1;
    const int bh = tid & 1;

    float acc[2][4][4];
#pragma unroll
    for (int i = 0; i < 2; ++i)
#pragma unroll
        for (int j = 0; j < 4; ++j)
#pragma unroll
            for (int r = 0; r < 4; ++r) acc[i][j][r] = 0.f;

    // ---- induction state for the producer: recomputed once per DIRECTION (7x), not per chunk ----
    int lnd = 0;                       // direction of the next load
    int lc0 = 0;                       // K offset of the next load within the direction
    const __half* asrc = g_xt;         // A source base for this thread, current direction
    bool aok = false;
    auto set_dir = [&](int nd) {
        const int hh = ah_ + cDY[nd];
        const int ww = aw_ + cDX[nd];
        const bool hv = ((unsigned)hh < HH);
        const int wmn = hv ? hx_wmin(hh) : 0;
        aok = aiv && hv && (ww >= wmn) && (ww <= (hv ? hx_wmax(hh) : -1));
        const int src = aok ? (hx_rowstart(hh) + ww - wmn) : 0;
        asrc = g_xt + ((size_t)b * NVP + src) * CIN + akc * 8;
    };
    if (aown) set_dir(0);
    const __half* bptr = g_w + (size_t)br * CIN + bh * 16;  // advances by COUT*CIN per direction

    // cheap per-chunk producer: pointer + small offset only
    auto do_load = [&](int s) {
        const uint32_t st = sb + (uint32_t)s * STAGE;
        if (aown)
            cpa16(st + am * RS + akc * 16, asrc + lc0, aok ? 16 : 0);
        const uint32_t bdst = st + A_BYTES + br * RS + bh * 32;
        cpa16(bdst,      bptr + lc0,     16);
        cpa16(bdst + 16, bptr + lc0 + 8, 16);
        lc0 += BK;
        if (lc0 == CIN) {               // direction boundary: 7 times total
            lc0 = 0;
            ++lnd;
            if (lnd < NDIR) {
                bptr += (size_t)COUT * CIN;
                if (aown) set_dir(lnd);
            }
        }
    };

    // hoisted lane-dependent LDSM offsets
    const uint32_t a_off = (uint32_t)((wm * 32 + (lane & 15)) * RS) + ((lane >> 4) << 4);
    const uint32_t b_off = A_BYTES
                         + (uint32_t)((wn * 32 + ((lane >> 4) << 3) + (lane & 7)) * RS)
                         + (((lane >> 3) & 1) << 4);

    auto compute_chunk = [&](int s) {
        const uint32_t st = sb + (uint32_t)s * STAGE;
        const uint32_t aaddr = st + a_off;
        const uint32_t baddr = st + b_off;
        uint32_t ah0[2][4], bb0[2][4], ah1[2][4], bb1[2][4];
        LDSM4(ah0[0], aaddr);
        LDSM4(ah0[1], aaddr + 16 * RS);
        LDSM4(bb0[0], baddr);
        LDSM4(bb0[1], baddr + 16 * RS);
        LDSM4(ah1[0], aaddr + 32);
        LDSM4(ah1[1], aaddr + 32 + 16 * RS);
        LDSM4(bb1[0], baddr + 32);
        LDSM4(bb1[1], baddr + 32 + 16 * RS);
#pragma unroll
        for (int mi = 0; mi < 2; ++mi)
#pragma unroll
            for (int ni = 0; ni < 4; ++ni)
                MMA(acc[mi][ni], ah0[mi], (&bb0[ni >> 1][(ni & 1) * 2]));
#pragma unroll
        for (int mi = 0; mi < 2; ++mi)
#pragma unroll
            for (int ni = 0; ni < 4; ++ni)
                MMA(acc[mi][ni], ah1[mi], (&bb1[ni >> 1][(ni & 1) * 2]));
    };

    // ---------------- 4-stage ring, 1 sync per chunk, 2 chunks in flight ----------------
    do_load(0); CP_COMMIT();
    do_load(1); CP_COMMIT();
    for (int ch = 0; ch < NCHUNK; ++ch) {
        if (ch + 2 < NCHUNK) do_load((ch + 2) & 3);
        CP_COMMIT();           // one group per iteration (empty near tail is fine)
        CP_WAIT2();            // group ch complete; ch+1, ch+2 may be outstanding
        __syncthreads();       // all warps see stage ch; also gates ring reuse
        compute_chunk(ch & 3);
    }

    // ---------------- epilogue: bias add (all compacted rows inside the hex) ----------------
    float bv[8];
#pragma unroll
    for (int ni = 0; ni < 4; ++ni)
#pragma unroll
        for (int j = 0; j < 2; ++j)
            bv[ni * 2 + j] = bias[wn * 32 + ni * 8 + (lane & 3) * 2 + j];

#pragma unroll
    for (int mi = 0; mi < 2; ++mi)
#pragma unroll
        for (int rh = 0; rh < 2; ++rh) {
            const int m = wm * 32 + mi * 16 + (lane >> 2) + rh * 8;
            const int ci = p0 + m;
            if (ci >= NV) continue;
            const int h = hx_h_of(ci);
            const int w = hx_wmin(h) + (ci - hx_rowstart(h));
            const int p = h * WW + w;
#pragma unroll
            for (int ni = 0; ni < 4; ++ni)
#pragma unroll
                for (int j = 0; j < 2; ++j) {
                    const int o = wn * 32 + ni * 8 + (lane & 3) * 2 + j;
                    out[((size_t)b * COUT + o) * NPIX + p] =
                        acc[mi][ni][rh * 2 + j] + bv[ni * 2 + j];
                }
        }
}

// ---------------- launch ----------------
extern "C" void kernel_launch(void* const* d_in, const int* in_sizes, int n_in,
                              void* d_out, int out_size) {
    const float* x    = (const float*)d_in[0];
    const float* wgt  = (const float*)d_in[1];
    const float* bias = (const float*)d_in[2];
    float* out = (float*)d_out;
    (void)in_sizes; (void)n_in; (void)out_size;

    cudaFuncSetAttribute(hexconv_mma, cudaFuncAttributeMaxDynamicSharedMemorySize, SMEM_BYTES);

    // launch order keeps the main kernel at position 3 (profiler window)
    zero_mask<<<BATCH * COUT, 256>>>(out);
    split_x_kernel<<<dim3(76, 8, BATCH), 256>>>(x);
    split_w_kernel<<<(NDIR * COUT * CIN + 255) / 256, 256>>>(wgt);
    hexconv_mma<<<dim3(MTILES, BATCH), THREADS, SMEM_BYTES>>>(bias, out);
}